// round 7
// baseline (speedup 1.0000x reference)
#include <cuda_runtime.h>
#include <math.h>

#define Sn   64
#define Bz   256
#define VIN  128
#define VOUTn 128
#define UU   1024
#define EE   512
#define TDEC 25
#define G3U  (3*UU)

// ---------------- scratch (static device globals; no allocation) ----------------
__device__ float g_gi_enc[(size_t)Sn*Bz*G3U];   // precomputed x@Wih^T + bih  [S,B,3U]
__device__ float g_enc_out[(size_t)Sn*Bz*UU];   // encoder outputs [S,B,U]
__device__ float g_enc_proj[(size_t)Sn*Bz*UU];  // enc_out @ W1^T + b [S,B,U]
__device__ float g_h[Bz*UU];                    // hidden state
__device__ float g_gh[Bz*G3U];                  // h @ Whh^T + bhh scratch
__device__ float g_gi_dec[Bz*G3U];              // gx @ dec_Wih^T + bih scratch
__device__ float g_q[Bz*UU];                    // h @ W2^T + b
__device__ float g_attn[Bz*Sn];                 // logits -> attn weights
__device__ float g_gx[Bz*(UU+EE)];              // [ctx | emb]
__device__ int   g_idx[Bz];                     // argmax token ids

// ---------------- generic fp32 GEMM: C[M,N] = A[M,K] @ W[N,K]^T + bias[N] ----------------
// Requires M%64==0, N%64==0, K%16==0 (true for all call sites).
__global__ void __launch_bounds__(256) gemm_abT(
    const float* __restrict__ A, const float* __restrict__ W,
    const float* __restrict__ bias, float* __restrict__ C,
    int M, int N, int K)
{
    __shared__ float As[16][64];
    __shared__ float Ws[16][64];
    const int bm  = blockIdx.y * 64;
    const int bn  = blockIdx.x * 64;
    const int tid = threadIdx.x;
    const int tm  = (tid >> 4) << 2;    // 0..60
    const int tn  = (tid & 15) << 2;    // 0..60
    const int lr  = tid >> 2;           // 0..63 (tile row for loads)
    const int lk  = (tid & 3) << 2;     // 0,4,8,12 (k offset for float4 loads)

    float acc[4][4];
    #pragma unroll
    for (int i = 0; i < 4; i++)
        #pragma unroll
        for (int j = 0; j < 4; j++) acc[i][j] = 0.f;

    for (int k0 = 0; k0 < K; k0 += 16) {
        float4 av = *(const float4*)(A + (size_t)(bm + lr) * K + k0 + lk);
        float4 wv = *(const float4*)(W + (size_t)(bn + lr) * K + k0 + lk);
        As[lk+0][lr] = av.x; As[lk+1][lr] = av.y; As[lk+2][lr] = av.z; As[lk+3][lr] = av.w;
        Ws[lk+0][lr] = wv.x; Ws[lk+1][lr] = wv.y; Ws[lk+2][lr] = wv.z; Ws[lk+3][lr] = wv.w;
        __syncthreads();
        #pragma unroll
        for (int kk = 0; kk < 16; kk++) {
            float4 a = *(const float4*)&As[kk][tm];
            float4 w = *(const float4*)&Ws[kk][tn];
            acc[0][0] += a.x*w.x; acc[0][1] += a.x*w.y; acc[0][2] += a.x*w.z; acc[0][3] += a.x*w.w;
            acc[1][0] += a.y*w.x; acc[1][1] += a.y*w.y; acc[1][2] += a.y*w.z; acc[1][3] += a.y*w.w;
            acc[2][0] += a.z*w.x; acc[2][1] += a.z*w.y; acc[2][2] += a.z*w.z; acc[2][3] += a.z*w.w;
            acc[3][0] += a.w*w.x; acc[3][1] += a.w*w.y; acc[3][2] += a.w*w.z; acc[3][3] += a.w*w.w;
        }
        __syncthreads();
    }

    #pragma unroll
    for (int i = 0; i < 4; i++) {
        size_t row = (size_t)(bm + tm + i) * N + bn + tn;
        #pragma unroll
        for (int j = 0; j < 4; j++)
            C[row + j] = acc[i][j] + bias[bn + tn + j];
    }
}

// ---------------- GRU gate fusions ----------------
__device__ __forceinline__ float sigm(float v) { return 1.f / (1.f + expf(-v)); }

__global__ void enc_gate(const float* __restrict__ gi, const float* __restrict__ gh,
                         float* __restrict__ h, float* __restrict__ enc_out_t,
                         const int* __restrict__ x_len, int t)
{
    int i = blockIdx.x * blockDim.x + threadIdx.x;       // b*U+u
    if (i >= Bz*UU) return;
    int b = i / UU, u = i % UU;
    size_t base = (size_t)b * G3U;
    float r = sigm(gi[base + u]        + gh[base + u]);
    float z = sigm(gi[base + UU + u]   + gh[base + UU + u]);
    float n = tanhf(gi[base + 2*UU + u] + r * gh[base + 2*UU + u]);
    float hv   = h[i];
    float hnew = (1.f - z) * n + z * hv;
    bool  m    = t < x_len[b];
    h[i]         = m ? hnew : hv;
    enc_out_t[i] = m ? hnew : 0.f;
}

__global__ void dec_gate(const float* __restrict__ gi, const float* __restrict__ gh,
                         float* __restrict__ h)
{
    int i = blockIdx.x * blockDim.x + threadIdx.x;
    if (i >= Bz*UU) return;
    int b = i / UU, u = i % UU;
    size_t base = (size_t)b * G3U;
    float r = sigm(gi[base + u]        + gh[base + u]);
    float z = sigm(gi[base + UU + u]   + gh[base + UU + u]);
    float n = tanhf(gi[base + 2*UU + u] + r * gh[base + 2*UU + u]);
    h[i] = (1.f - z) * n + z * h[i];
}

// ---------------- attention ----------------
// logits[b,s] = V_b + sum_u tanh(enc_proj[s,b,u] + q[b,u]) * V_W[u]
__global__ void attn_logits(const float* __restrict__ enc_proj,
                            const float* __restrict__ q,
                            const float* __restrict__ V_W,
                            const float* __restrict__ V_b,
                            float* __restrict__ logits)
{
    int bs = blockIdx.x;            // b*S + s
    int b = bs / Sn, s = bs % Sn;
    const float* ep = enc_proj + ((size_t)s * Bz + b) * UU;
    const float* qb = q + (size_t)b * UU;
    float sum = 0.f;
    for (int u = threadIdx.x; u < UU; u += 128)
        sum += tanhf(ep[u] + qb[u]) * V_W[u];
    // reduce 128 -> 1
    #pragma unroll
    for (int off = 16; off; off >>= 1)
        sum += __shfl_down_sync(0xffffffffu, sum, off);
    __shared__ float ws[4];
    int lane = threadIdx.x & 31, wid = threadIdx.x >> 5;
    if (lane == 0) ws[wid] = sum;
    __syncthreads();
    if (threadIdx.x == 0)
        logits[(size_t)b * Sn + s] = ws[0] + ws[1] + ws[2] + ws[3] + V_b[0];
}

__global__ void softmax_s(float* __restrict__ logits)
{
    int b = blockIdx.x;
    int s = threadIdx.x;            // 64 threads
    __shared__ float sm[Sn];
    float v = logits[(size_t)b * Sn + s];
    sm[s] = v; __syncthreads();
    #pragma unroll
    for (int off = 32; off; off >>= 1) { if (s < off) sm[s] = fmaxf(sm[s], sm[s+off]); __syncthreads(); }
    float mx = sm[0]; __syncthreads();
    float e = expf(v - mx);
    sm[s] = e; __syncthreads();
    #pragma unroll
    for (int off = 32; off; off >>= 1) { if (s < off) sm[s] += sm[s+off]; __syncthreads(); }
    logits[(size_t)b * Sn + s] = e / sm[0];
}

// ctx[b,u] = sum_s attn[b,s] * enc_out[s,b,u]  -> gx[b, 0..U)
__global__ void ctx_kernel(const float* __restrict__ attn,
                           const float* __restrict__ enc_out,
                           float* __restrict__ gx)
{
    int i = blockIdx.x * blockDim.x + threadIdx.x;   // b*U+u
    if (i >= Bz*UU) return;
    int b = i / UU, u = i % UU;
    const float* eo = enc_out + (size_t)b * UU + u;
    const float* at = attn + (size_t)b * Sn;
    float sum = 0.f;
    #pragma unroll 8
    for (int t = 0; t < Sn; t++)
        sum += at[t] * eo[(size_t)t * Bz * UU];
    gx[(size_t)b * (UU+EE) + u] = sum;
}

// emb[b,e] = o2h_W[e, idx[b]] + o2h_b[e]  -> gx[b, U..U+E)
__global__ void emb_kernel(const int* __restrict__ idx,
                           const float* __restrict__ o2h_W,
                           const float* __restrict__ o2h_b,
                           float* __restrict__ gx)
{
    int i = blockIdx.x * blockDim.x + threadIdx.x;   // b*E+e
    if (i >= Bz*EE) return;
    int b = i / EE, e = i % EE;
    gx[(size_t)b * (UU+EE) + UU + e] = o2h_W[(size_t)e * VOUTn + idx[b]] + o2h_b[e];
}

__global__ void argmax128(const float* __restrict__ pred, int* __restrict__ idx)
{
    int b = blockIdx.x;
    int t = threadIdx.x;            // 128 threads
    __shared__ float sv[VOUTn];
    __shared__ int   si[VOUTn];
    sv[t] = pred[(size_t)b * VOUTn + t];
    si[t] = t;
    __syncthreads();
    #pragma unroll
    for (int off = 64; off; off >>= 1) {
        if (t < off) {
            float v2 = sv[t+off]; int i2 = si[t+off];
            if (v2 > sv[t] || (v2 == sv[t] && i2 < si[t])) { sv[t] = v2; si[t] = i2; }
        }
        __syncthreads();
    }
    if (t == 0) idx[b] = si[0];
}

__global__ void init_state(float* __restrict__ h, float* __restrict__ out0,
                           int* __restrict__ idx)
{
    int i = blockIdx.x * blockDim.x + threadIdx.x;
    if (i < Bz*UU)    h[i] = 0.f;
    if (i < Bz*VOUTn) out0[i] = ((i % VOUTn) == 0) ? 1.f : 0.f;   // one-hot START_CODE=0
    if (i < Bz)       idx[i] = 0;
}

// ---------------- driver ----------------
extern "C" void kernel_launch(void* const* d_in, const int* in_sizes, int n_in,
                              void* d_out, int out_size)
{
    const float* x       = (const float*)d_in[0];
    const int*   x_len   = (const int*)  d_in[1];
    const float* enc_Wih = (const float*)d_in[2];
    const float* enc_Whh = (const float*)d_in[3];
    const float* enc_bih = (const float*)d_in[4];
    const float* enc_bhh = (const float*)d_in[5];
    const float* dec_Wih = (const float*)d_in[6];
    const float* dec_Whh = (const float*)d_in[7];
    const float* dec_bih = (const float*)d_in[8];
    const float* dec_bhh = (const float*)d_in[9];
    const float* o2h_W   = (const float*)d_in[10];
    const float* o2h_b   = (const float*)d_in[11];
    const float* fc_W    = (const float*)d_in[12];
    const float* fc_b    = (const float*)d_in[13];
    const float* W1_W    = (const float*)d_in[14];
    const float* W1_b    = (const float*)d_in[15];
    const float* W2_W    = (const float*)d_in[16];
    const float* W2_b    = (const float*)d_in[17];
    const float* V_W     = (const float*)d_in[18];
    const float* V_b     = (const float*)d_in[19];
    float* out = (float*)d_out;

    float *gi_enc, *enc_out, *enc_proj, *h, *gh, *gi_dec, *q, *attn, *gx;
    int* idx;
    cudaGetSymbolAddress((void**)&gi_enc,   g_gi_enc);
    cudaGetSymbolAddress((void**)&enc_out,  g_enc_out);
    cudaGetSymbolAddress((void**)&enc_proj, g_enc_proj);
    cudaGetSymbolAddress((void**)&h,        g_h);
    cudaGetSymbolAddress((void**)&gh,       g_gh);
    cudaGetSymbolAddress((void**)&gi_dec,   g_gi_dec);
    cudaGetSymbolAddress((void**)&q,        g_q);
    cudaGetSymbolAddress((void**)&attn,     g_attn);
    cudaGetSymbolAddress((void**)&gx,       g_gx);
    cudaGetSymbolAddress((void**)&idx,      g_idx);

    dim3 blk(256);

    // Precompute encoder input gates for ALL timesteps in one big GEMM.
    gemm_abT<<<dim3(G3U/64, (Sn*Bz)/64), blk>>>(x, enc_Wih, enc_bih, gi_enc,
                                                Sn*Bz, G3U, VIN);
    init_state<<<(Bz*UU + 255)/256, 256>>>(h, out, idx);

    // ---- Encoder: 64 sequential GRU steps ----
    for (int t = 0; t < Sn; t++) {
        gemm_abT<<<dim3(G3U/64, Bz/64), blk>>>(h, enc_Whh, enc_bhh, gh, Bz, G3U, UU);
        enc_gate<<<(Bz*UU)/256, 256>>>(gi_enc + (size_t)t*Bz*G3U, gh, h,
                                       enc_out + (size_t)t*Bz*UU, x_len, t);
    }

    // enc_proj = enc_out @ W1^T + b  (flattened over [S*B, U])
    gemm_abT<<<dim3(UU/64, (Sn*Bz)/64), blk>>>(enc_out, W1_W, W1_b, enc_proj,
                                               Sn*Bz, UU, UU);

    // ---- Decoder: 24 sequential attention+GRU steps ----
    for (int t = 0; t < TDEC - 1; t++) {
        gemm_abT<<<dim3(UU/64, Bz/64), blk>>>(h, W2_W, W2_b, q, Bz, UU, UU);
        attn_logits<<<Bz*Sn, 128>>>(enc_proj, q, V_W, V_b, attn);
        softmax_s<<<Bz, Sn>>>(attn);
        ctx_kernel<<<(Bz*UU)/256, 256>>>(attn, enc_out, gx);
        emb_kernel<<<(Bz*EE)/256, 256>>>(idx, o2h_W, o2h_b, gx);
        gemm_abT<<<dim3(G3U/64, Bz/64), blk>>>(gx, dec_Wih, dec_bih, gi_dec,
                                               Bz, G3U, UU+EE);
        gemm_abT<<<dim3(G3U/64, Bz/64), blk>>>(h, dec_Whh, dec_bhh, gh, Bz, G3U, UU);
        dec_gate<<<(Bz*UU)/256, 256>>>(gi_dec, gh, h);
        gemm_abT<<<dim3(VOUTn/64, Bz/64), blk>>>(h, fc_W, fc_b,
                                                 out + (size_t)(t+1)*Bz*VOUTn,
                                                 Bz, VOUTn, UU);
        argmax128<<<Bz, 128>>>(out + (size_t)(t+1)*Bz*VOUTn, idx);
    }
}

// round 8
// speedup vs baseline: 1.7050x; 1.7050x over previous
#include <cuda_runtime.h>
#include <math.h>

typedef unsigned long long ull;

#define Sn    64
#define Bz    256
#define VIN   128
#define VOUTn 128
#define UU    1024
#define EE    512
#define TDEC  25
#define G3U   (3*UU)
#define GHKS  3
#define GIKS  3
#define QKS   3
#define FCKS  8

// ---------------- scratch (static device globals; no allocation) ----------------
__device__ float g_gi_enc[(size_t)Sn*Bz*G3U];     // x@Wih^T + bih  [S,B,3U]
__device__ float g_enc_out[(size_t)Sn*Bz*UU];     // encoder outputs [S,B,U]
__device__ float g_enc_proj[(size_t)Sn*Bz*UU];    // enc_out @ W1^T + b [S,B,U]
__device__ float g_h[Bz*UU];
__device__ float g_ghp[(size_t)GHKS*Bz*G3U];      // split-K partials of h@Whh^T
__device__ float g_gip[(size_t)GIKS*Bz*G3U];      // split-K partials of gx@dec_Wih^T
__device__ float g_qp[(size_t)QKS*Bz*UU];         // split-K partials of h@W2^T
__device__ float g_q[Bz*UU];
__device__ float g_attn[Bz*Sn];
__device__ float g_gx[Bz*(UU+EE)];
__device__ float g_fcp[(size_t)FCKS*Bz*VOUTn];    // split-K partials of h@fc^T
__device__ int   g_idx[Bz];

// ---------------- fast (but ~1e-7-accurate) transcendentals ----------------
__device__ __forceinline__ float f_ex2(float x){ float r; asm("ex2.approx.f32 %0, %1;" : "=f"(r) : "f"(x)); return r; }
__device__ __forceinline__ float f_rcp(float x){ float r; asm("rcp.approx.f32 %0, %1;" : "=f"(r) : "f"(x)); return r; }
__device__ __forceinline__ float fsigm(float x){ return f_rcp(1.f + f_ex2(-1.4426950408889634f*x)); }
__device__ __forceinline__ float ftanh(float x){ return 1.f - 2.f*f_rcp(1.f + f_ex2(2.8853900817779268f*x)); }

// ---------------- f32x2 helpers ----------------
#define DUP2(d, s)      asm("mov.b64 %0, {%1, %1};" : "=l"(d) : "f"(s))
#define FMA2(c, a, b)   asm("fma.rn.f32x2 %0, %1, %2, %0;" : "+l"(c) : "l"(a), "l"(b))
#define UNPK2(lo, hi, s) asm("mov.b64 {%0, %1}, %2;" : "=f"(lo), "=f"(hi) : "l"(s))

// ---------------- FFMA2 GEMM: C[M,N] = A[M,K] @ W[N,K]^T (+bias on slice 0) ----
// Block tile 64(M) x 128(N), 128 threads, thread tile 8x8 (M paired into f32x2).
// grid = (N/128, M/64, KS); slice z writes C + z*M*N over k-range [nslab*z/KS, ...).
// Requires M%64==0, N%128==0, K%16==0.
__global__ void __launch_bounds__(128) gemm2(
    const float* __restrict__ A, const float* __restrict__ W,
    const float* __restrict__ bias, float* __restrict__ C,
    int M, int N, int K, int KS)
{
    __shared__ float As[16][64];      // k-major, m contiguous
    __shared__ float Ws[16][128];     // k-major, n contiguous

    const int nslab = K >> 4;
    const int z  = blockIdx.z;
    const int k0 = ((nslab *  z     ) / KS) << 4;
    const int k1 = ((nslab * (z + 1)) / KS) << 4;
    C += (size_t)z * M * N;

    const int bm  = blockIdx.y * 64;
    const int bn  = blockIdx.x * 128;
    const int tid = threadIdx.x;
    const int ty  = tid >> 4;               // 0..7  -> 8 m-rows (4 pairs)
    const int tx  = tid & 15;               // 0..15 -> 8 n-cols
    const int ar  = tid >> 1;               // 0..63 A load row
    const int ak  = (tid & 1) << 3;         // 0/8   A load k offset

    ull acc[4][8];
    #pragma unroll
    for (int i = 0; i < 4; i++)
        #pragma unroll
        for (int j = 0; j < 8; j++) acc[i][j] = 0ull;

    const float* Arow = A + (size_t)(bm + ar) * K + ak;
    const float* Wrow = W + (size_t)(bn + tid) * K;

    for (int kb = k0; kb < k1; kb += 16) {
        float4 a0 = *(const float4*)(Arow + kb);
        float4 a1 = *(const float4*)(Arow + kb + 4);
        As[ak+0][ar] = a0.x; As[ak+1][ar] = a0.y; As[ak+2][ar] = a0.z; As[ak+3][ar] = a0.w;
        As[ak+4][ar] = a1.x; As[ak+5][ar] = a1.y; As[ak+6][ar] = a1.z; As[ak+7][ar] = a1.w;
        float4 w0 = *(const float4*)(Wrow + kb);
        float4 w1 = *(const float4*)(Wrow + kb + 4);
        float4 w2 = *(const float4*)(Wrow + kb + 8);
        float4 w3 = *(const float4*)(Wrow + kb + 12);
        Ws[ 0][tid] = w0.x; Ws[ 1][tid] = w0.y; Ws[ 2][tid] = w0.z; Ws[ 3][tid] = w0.w;
        Ws[ 4][tid] = w1.x; Ws[ 5][tid] = w1.y; Ws[ 6][tid] = w1.z; Ws[ 7][tid] = w1.w;
        Ws[ 8][tid] = w2.x; Ws[ 9][tid] = w2.y; Ws[10][tid] = w2.z; Ws[11][tid] = w2.w;
        Ws[12][tid] = w3.x; Ws[13][tid] = w3.y; Ws[14][tid] = w3.z; Ws[15][tid] = w3.w;
        __syncthreads();

        #pragma unroll
        for (int kk = 0; kk < 16; kk++) {
            const ull* ap = (const ull*)&As[kk][ty << 3];
            ull a2_0 = ap[0], a2_1 = ap[1], a2_2 = ap[2], a2_3 = ap[3];
            const float* wp = &Ws[kk][tx << 3];
            float4 wv0 = *(const float4*)wp;
            float4 wv1 = *(const float4*)(wp + 4);
            ull wd[8];
            DUP2(wd[0], wv0.x); DUP2(wd[1], wv0.y); DUP2(wd[2], wv0.z); DUP2(wd[3], wv0.w);
            DUP2(wd[4], wv1.x); DUP2(wd[5], wv1.y); DUP2(wd[6], wv1.z); DUP2(wd[7], wv1.w);
            #pragma unroll
            for (int j = 0; j < 8; j++) {
                FMA2(acc[0][j], a2_0, wd[j]);
                FMA2(acc[1][j], a2_1, wd[j]);
                FMA2(acc[2][j], a2_2, wd[j]);
                FMA2(acc[3][j], a2_3, wd[j]);
            }
        }
        __syncthreads();
    }

    const int col = bn + (tx << 3);
    float bv[8];
    #pragma unroll
    for (int j = 0; j < 8; j++) bv[j] = (z == 0) ? bias[col + j] : 0.f;

    #pragma unroll
    for (int i = 0; i < 4; i++) {
        const int r0 = bm + (ty << 3) + 2*i;
        float lo[8], hi[8];
        #pragma unroll
        for (int j = 0; j < 8; j++) {
            float l, h;
            UNPK2(l, h, acc[i][j]);
            lo[j] = l + bv[j];
            hi[j] = h + bv[j];
        }
        float4* c0 = (float4*)(C + (size_t)r0     * N + col);
        float4* c1 = (float4*)(C + (size_t)(r0+1) * N + col);
        c0[0] = make_float4(lo[0], lo[1], lo[2], lo[3]);
        c0[1] = make_float4(lo[4], lo[5], lo[6], lo[7]);
        c1[0] = make_float4(hi[0], hi[1], hi[2], hi[3]);
        c1[1] = make_float4(hi[4], hi[5], hi[6], hi[7]);
    }
}

// ---------------- GRU gates (consume split-K partials) ----------------
__global__ void enc_gate(const float* __restrict__ gi, const float* __restrict__ ghp,
                         float* __restrict__ h, float* __restrict__ enc_out_t,
                         const int* __restrict__ x_len, int t)
{
    int i = blockIdx.x * blockDim.x + threadIdx.x;       // b*U+u
    int b = i >> 10, u = i & (UU-1);
    size_t base = (size_t)b * G3U + u;
    const size_t MN = (size_t)Bz * G3U;
    float ghr = 0.f, ghz = 0.f, ghn = 0.f;
    #pragma unroll
    for (int s = 0; s < GHKS; s++) {
        ghr += ghp[s*MN + base];
        ghz += ghp[s*MN + base + UU];
        ghn += ghp[s*MN + base + 2*UU];
    }
    float r = fsigm(gi[base]        + ghr);
    float z = fsigm(gi[base + UU]   + ghz);
    float n = ftanh(gi[base + 2*UU] + r * ghn);
    float hv   = h[i];
    float hnew = (1.f - z) * n + z * hv;
    bool  m    = t < x_len[b];
    h[i]         = m ? hnew : hv;
    enc_out_t[i] = m ? hnew : 0.f;
}

__global__ void dec_gate(const float* __restrict__ gip, const float* __restrict__ ghp,
                         float* __restrict__ h)
{
    int i = blockIdx.x * blockDim.x + threadIdx.x;
    int b = i >> 10, u = i & (UU-1);
    size_t base = (size_t)b * G3U + u;
    const size_t MN = (size_t)Bz * G3U;
    float gir = 0.f, giz = 0.f, gin = 0.f, ghr = 0.f, ghz = 0.f, ghn = 0.f;
    #pragma unroll
    for (int s = 0; s < GIKS; s++) {
        gir += gip[s*MN + base];
        giz += gip[s*MN + base + UU];
        gin += gip[s*MN + base + 2*UU];
    }
    #pragma unroll
    for (int s = 0; s < GHKS; s++) {
        ghr += ghp[s*MN + base];
        ghz += ghp[s*MN + base + UU];
        ghn += ghp[s*MN + base + 2*UU];
    }
    float r = fsigm(gir + ghr);
    float z = fsigm(giz + ghz);
    float n = ftanh(gin + r * ghn);
    h[i] = (1.f - z) * n + z * h[i];
}

// ---------------- sum q partials ----------------
__global__ void qsum(const float* __restrict__ qp, float* __restrict__ q)
{
    int i = blockIdx.x * blockDim.x + threadIdx.x;       // float4 index
    const size_t MN4 = (size_t)Bz * UU / 4;
    float4 a = ((const float4*)qp)[i];
    float4 b = ((const float4*)qp)[MN4 + i];
    float4 c = ((const float4*)qp)[2*MN4 + i];
    ((float4*)q)[i] = make_float4(a.x+b.x+c.x, a.y+b.y+c.y, a.z+b.z+c.z, a.w+b.w+c.w);
}

// ---------------- attention ----------------
__global__ void attn_logits(const float* __restrict__ enc_proj,
                            const float* __restrict__ q,
                            const float* __restrict__ V_W,
                            const float* __restrict__ V_b,
                            float* __restrict__ logits)
{
    int bs = blockIdx.x;            // b*S + s
    int b = bs >> 6, s = bs & 63;
    const float4* ep4 = (const float4*)(enc_proj + ((size_t)s * Bz + b) * UU);
    const float4* q4  = (const float4*)(q + (size_t)b * UU);
    const float4* vw4 = (const float4*)V_W;
    float sum = 0.f;
    #pragma unroll
    for (int it = 0; it < UU/4/128; it++) {
        int u4 = it * 128 + threadIdx.x;
        float4 e = ep4[u4], qq = q4[u4], vw = vw4[u4];
        sum += ftanh(e.x + qq.x) * vw.x + ftanh(e.y + qq.y) * vw.y
             + ftanh(e.z + qq.z) * vw.z + ftanh(e.w + qq.w) * vw.w;
    }
    #pragma unroll
    for (int off = 16; off; off >>= 1)
        sum += __shfl_down_sync(0xffffffffu, sum, off);
    __shared__ float ws[4];
    int lane = threadIdx.x & 31, wid = threadIdx.x >> 5;
    if (lane == 0) ws[wid] = sum;
    __syncthreads();
    if (threadIdx.x == 0)
        logits[(size_t)b * Sn + s] = ws[0] + ws[1] + ws[2] + ws[3] + V_b[0];
}

__global__ void softmax_s(float* __restrict__ logits)
{
    int b = blockIdx.x;
    int s = threadIdx.x;            // 64 threads
    __shared__ float sm[Sn];
    float v = logits[(size_t)b * Sn + s];
    sm[s] = v; __syncthreads();
    #pragma unroll
    for (int off = 32; off; off >>= 1) { if (s < off) sm[s] = fmaxf(sm[s], sm[s+off]); __syncthreads(); }
    float mx = sm[0]; __syncthreads();
    float e = expf(v - mx);
    sm[s] = e; __syncthreads();
    #pragma unroll
    for (int off = 32; off; off >>= 1) { if (s < off) sm[s] += sm[s+off]; __syncthreads(); }
    logits[(size_t)b * Sn + s] = e / sm[0];
}

__global__ void ctx_kernel(const float* __restrict__ attn,
                           const float* __restrict__ enc_out,
                           float* __restrict__ gx)
{
    int i = blockIdx.x * blockDim.x + threadIdx.x;   // b*U+u
    int b = i >> 10, u = i & (UU-1);
    const float* eo = enc_out + (size_t)b * UU + u;
    const float* at = attn + (size_t)b * Sn;
    float sum = 0.f;
    #pragma unroll 8
    for (int t = 0; t < Sn; t++)
        sum += at[t] * eo[(size_t)t * Bz * UU];
    gx[(size_t)b * (UU+EE) + u] = sum;
}

__global__ void emb_kernel(const int* __restrict__ idx,
                           const float* __restrict__ o2h_W,
                           const float* __restrict__ o2h_b,
                           float* __restrict__ gx)
{
    int i = blockIdx.x * blockDim.x + threadIdx.x;   // b*E+e
    int b = i / EE, e = i % EE;
    gx[(size_t)b * (UU+EE) + UU + e] = o2h_W[(size_t)e * VOUTn + idx[b]] + o2h_b[e];
}

// sum fc partials -> pred, write output slice, argmax (first-max tiebreak)
__global__ void pred_argmax(const float* __restrict__ fcp,
                            float* __restrict__ out_t, int* __restrict__ idx)
{
    int b = blockIdx.x;
    int t = threadIdx.x;            // 128 threads
    const size_t MN = (size_t)Bz * VOUTn;
    float v = 0.f;
    #pragma unroll
    for (int s = 0; s < FCKS; s++) v += fcp[s*MN + (size_t)b * VOUTn + t];
    out_t[(size_t)b * VOUTn + t] = v;

    __shared__ float sv[VOUTn];
    __shared__ int   si[VOUTn];
    sv[t] = v; si[t] = t;
    __syncthreads();
    #pragma unroll
    for (int off = 64; off; off >>= 1) {
        if (t < off) {
            float v2 = sv[t+off]; int i2 = si[t+off];
            if (v2 > sv[t] || (v2 == sv[t] && i2 < si[t])) { sv[t] = v2; si[t] = i2; }
        }
        __syncthreads();
    }
    if (t == 0) idx[b] = si[0];
}

__global__ void init_state(float* __restrict__ h, float* __restrict__ out0,
                           int* __restrict__ idx)
{
    int i = blockIdx.x * blockDim.x + threadIdx.x;
    if (i < Bz*UU)    h[i] = 0.f;
    if (i < Bz*VOUTn) out0[i] = ((i % VOUTn) == 0) ? 1.f : 0.f;
    if (i < Bz)       idx[i] = 0;
}

// ---------------- driver ----------------
extern "C" void kernel_launch(void* const* d_in, const int* in_sizes, int n_in,
                              void* d_out, int out_size)
{
    const float* x       = (const float*)d_in[0];
    const int*   x_len   = (const int*)  d_in[1];
    const float* enc_Wih = (const float*)d_in[2];
    const float* enc_Whh = (const float*)d_in[3];
    const float* enc_bih = (const float*)d_in[4];
    const float* enc_bhh = (const float*)d_in[5];
    const float* dec_Wih = (const float*)d_in[6];
    const float* dec_Whh = (const float*)d_in[7];
    const float* dec_bih = (const float*)d_in[8];
    const float* dec_bhh = (const float*)d_in[9];
    const float* o2h_W   = (const float*)d_in[10];
    const float* o2h_b   = (const float*)d_in[11];
    const float* fc_W    = (const float*)d_in[12];
    const float* fc_b    = (const float*)d_in[13];
    const float* W1_W    = (const float*)d_in[14];
    const float* W1_b    = (const float*)d_in[15];
    const float* W2_W    = (const float*)d_in[16];
    const float* W2_b    = (const float*)d_in[17];
    const float* V_W     = (const float*)d_in[18];
    const float* V_b     = (const float*)d_in[19];
    float* out = (float*)d_out;

    float *gi_enc, *enc_out, *enc_proj, *h, *ghp, *gip, *qp, *q, *attn, *gx, *fcp;
    int* idx;
    cudaGetSymbolAddress((void**)&gi_enc,   g_gi_enc);
    cudaGetSymbolAddress((void**)&enc_out,  g_enc_out);
    cudaGetSymbolAddress((void**)&enc_proj, g_enc_proj);
    cudaGetSymbolAddress((void**)&h,        g_h);
    cudaGetSymbolAddress((void**)&ghp,      g_ghp);
    cudaGetSymbolAddress((void**)&gip,      g_gip);
    cudaGetSymbolAddress((void**)&qp,       g_qp);
    cudaGetSymbolAddress((void**)&q,        g_q);
    cudaGetSymbolAddress((void**)&attn,     g_attn);
    cudaGetSymbolAddress((void**)&gx,       g_gx);
    cudaGetSymbolAddress((void**)&fcp,      g_fcp);
    cudaGetSymbolAddress((void**)&idx,      g_idx);

    // Precompute encoder input gates for all timesteps: [S*B, 3U] = [S*B,128] @ [3U,128]^T
    gemm2<<<dim3(G3U/128, (Sn*Bz)/64, 1), 128>>>(x, enc_Wih, enc_bih, gi_enc,
                                                 Sn*Bz, G3U, VIN, 1);
    init_state<<<(Bz*UU + 255)/256, 256>>>(h, out, idx);

    // ---- Encoder: 64 sequential GRU steps ----
    for (int t = 0; t < Sn; t++) {
        gemm2<<<dim3(G3U/128, Bz/64, GHKS), 128>>>(h, enc_Whh, enc_bhh, ghp,
                                                   Bz, G3U, UU, GHKS);
        enc_gate<<<(Bz*UU)/256, 256>>>(gi_enc + (size_t)t*Bz*G3U, ghp, h,
                                       enc_out + (size_t)t*Bz*UU, x_len, t);
    }

    // enc_proj = enc_out @ W1^T + b
    gemm2<<<dim3(UU/128, (Sn*Bz)/64, 1), 128>>>(enc_out, W1_W, W1_b, enc_proj,
                                                Sn*Bz, UU, UU, 1);

    // ---- Decoder: 24 sequential attention+GRU steps ----
    for (int t = 0; t < TDEC - 1; t++) {
        gemm2<<<dim3(UU/128, Bz/64, QKS), 128>>>(h, W2_W, W2_b, qp, Bz, UU, UU, QKS);
        qsum<<<(Bz*UU/4)/128, 128>>>(qp, q);
        attn_logits<<<Bz*Sn, 128>>>(enc_proj, q, V_W, V_b, attn);
        softmax_s<<<Bz, Sn>>>(attn);
        ctx_kernel<<<(Bz*UU)/256, 256>>>(attn, enc_out, gx);
        emb_kernel<<<(Bz*EE)/256, 256>>>(idx, o2h_W, o2h_b, gx);
        gemm2<<<dim3(G3U/128, Bz/64, GIKS), 128>>>(gx, dec_Wih, dec_bih, gip,
                                                   Bz, G3U, UU+EE, GIKS);
        gemm2<<<dim3(G3U/128, Bz/64, GHKS), 128>>>(h, dec_Whh, dec_bhh, ghp,
                                                   Bz, G3U, UU, GHKS);
        dec_gate<<<(Bz*UU)/256, 256>>>(gip, ghp, h);
        gemm2<<<dim3(VOUTn/128, Bz/64, FCKS), 128>>>(h, fc_W, fc_b, fcp,
                                                     Bz, VOUTn, UU, FCKS);
        pred_argmax<<<Bz, 128>>>(fcp, out + (size_t)(t+1)*Bz*VOUTn, idx);
    }
}

// round 9
// speedup vs baseline: 2.0348x; 1.1934x over previous
#include <cuda_runtime.h>
#include <math.h>

typedef unsigned long long ull;

#define Sn    64
#define Bz    256
#define VIN   128
#define VOUTn 128
#define UU    1024
#define EE    512
#define TDEC  25
#define G3U   3072
#define NQGH  4096
#define GHKS  3
#define GIKS  3
#define QGHKS 2
#define FCKS  16

// ---------------- scratch (static device globals; no allocation) ----------------
__device__ float g_gi_enc[(size_t)Sn*Bz*G3U];     // x@Wih^T + bih  [S,B,3U]
__device__ float g_enc_out[(size_t)Sn*Bz*UU];     // encoder outputs [S,B,U] (pre-zeroed)
__device__ float g_enc_proj[(size_t)Sn*Bz*UU];    // enc_out @ W1^T + b (active rows only)
__device__ float g_h[Bz*UU];
__device__ float g_ghp[(size_t)GHKS*Bz*G3U];      // split-K partials (encoder gh)
__device__ float g_gip[(size_t)GIKS*Bz*G3U];      // split-K partials (decoder gi, ctx part)
__device__ float g_qghp[(size_t)QGHKS*Bz*NQGH];   // split-K partials (decoder [gh|q])
__device__ float g_ctx[Bz*UU];
__device__ float g_fcp[(size_t)FCKS*Bz*VOUTn];
__device__ int   g_idx[Bz];
__device__ float g_Wqgh[(size_t)NQGH*UU];         // concat [dec_Whh; W2_W]
__device__ float g_bqgh[NQGH];                    // concat [dec_bhh; W2_b]
__device__ float g_T[(size_t)VOUTn*G3U];          // emb->gi table (incl dec_bih)
__device__ float g_Aemb[VOUTn*EE];                // (o2h_W^T + o2h_b) rows per token
__device__ float g_zero[G3U];                     // zero bias (stays 0)

// ---------------- fast (~1e-7-accurate) transcendentals ----------------
__device__ __forceinline__ float f_ex2(float x){ float r; asm("ex2.approx.f32 %0, %1;" : "=f"(r) : "f"(x)); return r; }
__device__ __forceinline__ float f_rcp(float x){ float r; asm("rcp.approx.f32 %0, %1;" : "=f"(r) : "f"(x)); return r; }
__device__ __forceinline__ float fsigm(float x){ return f_rcp(1.f + f_ex2(-1.4426950408889634f*x)); }
__device__ __forceinline__ float ftanh(float x){ return 1.f - 2.f*f_rcp(1.f + f_ex2(2.8853900817779268f*x)); }

// ---------------- f32x2 helpers ----------------
#define DUP2(d, s)       asm("mov.b64 %0, {%1, %1};" : "=l"(d) : "f"(s))
#define FMA2(c, a, b)    asm("fma.rn.f32x2 %0, %1, %2, %0;" : "+l"(c) : "l"(a), "l"(b))
#define UNPK2(lo, hi, s) asm("mov.b64 {%0, %1}, %2;" : "=f"(lo), "=f"(hi) : "l"(s))

// ---------------- FFMA2 GEMM: C[M,N] = A[M,K] @ W[N,K]^T (+bias on slice 0) ----
// Block 64(M)x128(N), 128 threads, thread tile 8x8 (M paired as f32x2).
// grid=(N/128, M/64, KS); slice z writes C + z*M*N.
// lda/ldw = row strides of A/W.  Early exit on sorted x_len:
//   tstep>=0: rows are batch b, skip if x_len[bm+63] <= tstep
//   tstep<0 : rows are s*256+b, skip if x_len[(bm&255)+63] <= (bm>>8)
__global__ void __launch_bounds__(128) gemm2(
    const float* __restrict__ A, int lda,
    const float* __restrict__ W, int ldw,
    const float* __restrict__ bias, float* __restrict__ C,
    int M, int N, int K, int KS,
    const int* __restrict__ x_len, int tstep)
{
    const int bm = blockIdx.y * 64;
    if (x_len) {
        int t_eff = (tstep >= 0) ? tstep : (bm >> 8);
        int b_hi  = (tstep >= 0) ? (bm + 63) : ((bm & 255) + 63);
        if (x_len[b_hi] <= t_eff) return;
    }

    __shared__ float As[16][64];
    __shared__ float Ws[16][128];

    const int nslab = K >> 4;
    const int z  = blockIdx.z;
    const int k0 = ((nslab *  z     ) / KS) << 4;
    const int k1 = ((nslab * (z + 1)) / KS) << 4;
    C += (size_t)z * M * N;

    const int bn  = blockIdx.x * 128;
    const int tid = threadIdx.x;
    const int ty  = tid >> 4;
    const int tx  = tid & 15;
    const int ar  = tid >> 1;
    const int ak  = (tid & 1) << 3;

    ull acc[4][8];
    #pragma unroll
    for (int i = 0; i < 4; i++)
        #pragma unroll
        for (int j = 0; j < 8; j++) acc[i][j] = 0ull;

    const float* Arow = A + (size_t)(bm + ar) * lda + ak;
    const float* Wrow = W + (size_t)(bn + tid) * ldw;

    float4 pa0 = *(const float4*)(Arow + k0);
    float4 pa1 = *(const float4*)(Arow + k0 + 4);
    float4 pw0 = *(const float4*)(Wrow + k0);
    float4 pw1 = *(const float4*)(Wrow + k0 + 4);
    float4 pw2 = *(const float4*)(Wrow + k0 + 8);
    float4 pw3 = *(const float4*)(Wrow + k0 + 12);

    for (int kb = k0; kb < k1; kb += 16) {
        As[ak+0][ar] = pa0.x; As[ak+1][ar] = pa0.y; As[ak+2][ar] = pa0.z; As[ak+3][ar] = pa0.w;
        As[ak+4][ar] = pa1.x; As[ak+5][ar] = pa1.y; As[ak+6][ar] = pa1.z; As[ak+7][ar] = pa1.w;
        Ws[ 0][tid] = pw0.x; Ws[ 1][tid] = pw0.y; Ws[ 2][tid] = pw0.z; Ws[ 3][tid] = pw0.w;
        Ws[ 4][tid] = pw1.x; Ws[ 5][tid] = pw1.y; Ws[ 6][tid] = pw1.z; Ws[ 7][tid] = pw1.w;
        Ws[ 8][tid] = pw2.x; Ws[ 9][tid] = pw2.y; Ws[10][tid] = pw2.z; Ws[11][tid] = pw2.w;
        Ws[12][tid] = pw3.x; Ws[13][tid] = pw3.y; Ws[14][tid] = pw3.z; Ws[15][tid] = pw3.w;
        __syncthreads();

        if (kb + 16 < k1) {        // prefetch next slab while computing
            pa0 = *(const float4*)(Arow + kb + 16);
            pa1 = *(const float4*)(Arow + kb + 20);
            pw0 = *(const float4*)(Wrow + kb + 16);
            pw1 = *(const float4*)(Wrow + kb + 20);
            pw2 = *(const float4*)(Wrow + kb + 24);
            pw3 = *(const float4*)(Wrow + kb + 28);
        }

        #pragma unroll
        for (int kk = 0; kk < 16; kk++) {
            const ull* ap = (const ull*)&As[kk][ty << 3];
            ull a2_0 = ap[0], a2_1 = ap[1], a2_2 = ap[2], a2_3 = ap[3];
            const float* wp = &Ws[kk][tx << 3];
            float4 wv0 = *(const float4*)wp;
            float4 wv1 = *(const float4*)(wp + 4);
            ull wd[8];
            DUP2(wd[0], wv0.x); DUP2(wd[1], wv0.y); DUP2(wd[2], wv0.z); DUP2(wd[3], wv0.w);
            DUP2(wd[4], wv1.x); DUP2(wd[5], wv1.y); DUP2(wd[6], wv1.z); DUP2(wd[7], wv1.w);
            #pragma unroll
            for (int j = 0; j < 8; j++) {
                FMA2(acc[0][j], a2_0, wd[j]);
                FMA2(acc[1][j], a2_1, wd[j]);
                FMA2(acc[2][j], a2_2, wd[j]);
                FMA2(acc[3][j], a2_3, wd[j]);
            }
        }
        __syncthreads();
    }

    const int col = bn + (tx << 3);
    float bv[8];
    #pragma unroll
    for (int j = 0; j < 8; j++) bv[j] = (z == 0) ? bias[col + j] : 0.f;

    #pragma unroll
    for (int i = 0; i < 4; i++) {
        const int r0 = bm + (ty << 3) + 2*i;
        float lo[8], hi[8];
        #pragma unroll
        for (int j = 0; j < 8; j++) {
            float l, h;
            UNPK2(l, h, acc[i][j]);
            lo[j] = l + bv[j];
            hi[j] = h + bv[j];
        }
        float4* c0 = (float4*)(C + (size_t)r0     * N + col);
        float4* c1 = (float4*)(C + (size_t)(r0+1) * N + col);
        c0[0] = make_float4(lo[0], lo[1], lo[2], lo[3]);
        c0[1] = make_float4(lo[4], lo[5], lo[6], lo[7]);
        c1[0] = make_float4(hi[0], hi[1], hi[2], hi[3]);
        c1[1] = make_float4(hi[4], hi[5], hi[6], hi[7]);
    }
}

// ---------------- encoder GRU gate (active rows only) ----------------
__global__ void enc_gate(const float* __restrict__ gi, const float* __restrict__ ghp,
                         float* __restrict__ h, float* __restrict__ enc_out_t,
                         const int* __restrict__ x_len, int t)
{
    int i = blockIdx.x * blockDim.x + threadIdx.x;       // b*U+u
    int b = i >> 10, u = i & (UU-1);
    if (t >= x_len[b]) return;                           // inactive: h frozen, enc_out stays 0
    size_t base = (size_t)b * G3U + u;
    const size_t MN = (size_t)Bz * G3U;
    float ghr = 0.f, ghz = 0.f, ghn = 0.f;
    #pragma unroll
    for (int s = 0; s < GHKS; s++) {
        ghr += ghp[s*MN + base];
        ghz += ghp[s*MN + base + UU];
        ghn += ghp[s*MN + base + 2*UU];
    }
    float r = fsigm(gi[base]        + ghr);
    float z = fsigm(gi[base + UU]   + ghz);
    float n = ftanh(gi[base + 2*UU] + r * ghn);
    float hnew = (1.f - z) * n + z * h[i];
    h[i]         = hnew;
    enc_out_t[i] = hnew;
}

// ---------------- decoder GRU gate (gi partials + emb table + qgh partials) ----
__global__ void dec_gate(const float* __restrict__ gip, const float* __restrict__ qghp,
                         const float* __restrict__ T, const int* __restrict__ idx,
                         float* __restrict__ h)
{
    int i = blockIdx.x * blockDim.x + threadIdx.x;
    int b = i >> 10, u = i & (UU-1);
    size_t gbase = (size_t)b * G3U + u;
    const size_t MN3 = (size_t)Bz * G3U;
    const float* tb = T + (size_t)idx[b] * G3U + u;
    float gir = tb[0], giz = tb[UU], gin = tb[2*UU];
    #pragma unroll
    for (int s = 0; s < GIKS; s++) {
        gir += gip[s*MN3 + gbase];
        giz += gip[s*MN3 + gbase + UU];
        gin += gip[s*MN3 + gbase + 2*UU];
    }
    size_t qbase = (size_t)b * NQGH + u;
    const size_t MNq = (size_t)Bz * NQGH;
    float ghr = 0.f, ghz = 0.f, ghn = 0.f;
    #pragma unroll
    for (int s = 0; s < QGHKS; s++) {
        ghr += qghp[s*MNq + qbase];
        ghz += qghp[s*MNq + qbase + UU];
        ghn += qghp[s*MNq + qbase + 2*UU];
    }
    float r = fsigm(gir + ghr);
    float z = fsigm(giz + ghz);
    float n = ftanh(gin + r * ghn);
    h[i] = (1.f - z) * n + z * h[i];
}

// ---------------- fused attention: q-sum + logits + softmax + ctx ----------------
// one block per batch element b, 256 threads (8 warps)
__global__ void __launch_bounds__(256) fused_attn(
    const float* __restrict__ qghp, const float* __restrict__ enc_proj,
    const float* __restrict__ enc_out,
    const float* __restrict__ V_W, const float* __restrict__ V_b,
    const float* __restrict__ W1_b, const int* __restrict__ x_len,
    float* __restrict__ ctx)
{
    __shared__ float qs[UU];
    __shared__ float vs[UU];
    __shared__ float wb[UU];
    __shared__ float lg[Sn];
    const int b = blockIdx.x, tid = threadIdx.x;
    const int w = tid >> 5, lane = tid & 31;
    const size_t MNq = (size_t)Bz * NQGH;
    const size_t qoff = (size_t)b * NQGH + 3*UU;

    #pragma unroll
    for (int k = 0; k < 4; k++) {
        int u = tid + 256*k;
        qs[u] = qghp[qoff + u] + qghp[MNq + qoff + u];   // q (bias in slice 0)
        vs[u] = V_W[u];
        wb[u] = W1_b[u];
    }
    __syncthreads();

    const int L = x_len[b];
    // real logits for active s
    for (int s = w; s < L; s += 8) {
        const float* ep = enc_proj + ((size_t)s * Bz + b) * UU;
        float sum = 0.f;
        #pragma unroll 4
        for (int u = lane; u < UU; u += 32)
            sum += ftanh(ep[u] + qs[u]) * vs[u];
        #pragma unroll
        for (int off = 16; off; off >>= 1)
            sum += __shfl_down_sync(0xffffffffu, sum, off);
        if (lane == 0) lg[s] = sum + V_b[0];
    }
    // constant logit for all masked s (enc_proj row == W1_b there)
    if (w == 0 && L < Sn) {
        float sum = 0.f;
        #pragma unroll 4
        for (int u = lane; u < UU; u += 32)
            sum += ftanh(wb[u] + qs[u]) * vs[u];
        #pragma unroll
        for (int off = 16; off; off >>= 1)
            sum += __shfl_down_sync(0xffffffffu, sum, off);
        if (lane == 0) {
            float c = sum + V_b[0];
            for (int s = L; s < Sn; s++) lg[s] = c;
        }
    }
    __syncthreads();

    // softmax over 64 logits (warp 0, 2 per lane)
    if (w == 0) {
        float v0 = lg[lane], v1 = lg[lane + 32];
        float mx = fmaxf(v0, v1);
        #pragma unroll
        for (int off = 16; off; off >>= 1)
            mx = fmaxf(mx, __shfl_xor_sync(0xffffffffu, mx, off));
        float e0 = f_ex2(1.4426950408889634f * (v0 - mx));
        float e1 = f_ex2(1.4426950408889634f * (v1 - mx));
        float sm = e0 + e1;
        #pragma unroll
        for (int off = 16; off; off >>= 1)
            sm += __shfl_xor_sync(0xffffffffu, sm, off);
        float inv = f_rcp(sm);
        lg[lane]      = e0 * inv;
        lg[lane + 32] = e1 * inv;
    }
    __syncthreads();

    // ctx: masked s contribute 0 (enc_out rows are zero) -> loop active s only
    float c0 = 0.f, c1 = 0.f, c2 = 0.f, c3 = 0.f;
    for (int s = 0; s < L; s++) {
        float a = lg[s];
        const float* eo = enc_out + ((size_t)s * Bz + b) * UU;
        c0 += a * eo[tid];
        c1 += a * eo[tid + 256];
        c2 += a * eo[tid + 512];
        c3 += a * eo[tid + 768];
    }
    float* cb = ctx + (size_t)b * UU;
    cb[tid] = c0; cb[tid + 256] = c1; cb[tid + 512] = c2; cb[tid + 768] = c3;
}

// ---------------- fc partial sum + output write + argmax ----------------
__global__ void pred_argmax(const float* __restrict__ fcp,
                            float* __restrict__ out_t, int* __restrict__ idx)
{
    int b = blockIdx.x;
    int t = threadIdx.x;            // 128 threads
    const size_t MN = (size_t)Bz * VOUTn;
    float v = 0.f;
    #pragma unroll
    for (int s = 0; s < FCKS; s++) v += fcp[s*MN + (size_t)b * VOUTn + t];
    out_t[(size_t)b * VOUTn + t] = v;

    __shared__ float sv[VOUTn];
    __shared__ int   si[VOUTn];
    sv[t] = v; si[t] = t;
    __syncthreads();
    #pragma unroll
    for (int off = 64; off; off >>= 1) {
        if (t < off) {
            float v2 = sv[t+off]; int i2 = si[t+off];
            if (v2 > sv[t] || (v2 == sv[t] && i2 < si[t])) { sv[t] = v2; si[t] = i2; }
        }
        __syncthreads();
    }
    if (t == 0) idx[b] = si[0];
}

// ---------------- one-time prep & init ----------------
__global__ void prep(const float* __restrict__ dec_Whh, const float* __restrict__ W2_W,
                     const float* __restrict__ dec_bhh, const float* __restrict__ W2_b,
                     const float* __restrict__ o2h_W,   const float* __restrict__ o2h_b,
                     float* __restrict__ Wqgh, float* __restrict__ bqgh,
                     float* __restrict__ Aemb)
{
    int i = blockIdx.x * 256 + threadIdx.x;          // 0 .. NQGH*UU-1
    Wqgh[i] = (i < G3U*UU) ? dec_Whh[i] : W2_W[i - G3U*UU];
    if (i < NQGH) bqgh[i] = (i < G3U) ? dec_bhh[i] : W2_b[i - G3U];
    if (i < VOUTn*EE) {
        int v = i / EE, e = i % EE;
        Aemb[i] = o2h_W[(size_t)e * VOUTn + v] + o2h_b[e];
    }
}

__global__ void init_all(float* __restrict__ enc_out, float* __restrict__ h,
                         float* __restrict__ out0, int* __restrict__ idx)
{
    size_t i = (size_t)blockIdx.x * 256 + threadIdx.x;    // 0 .. S*B*U-1
    enc_out[i] = 0.f;
    if (i < Bz*UU)    h[i] = 0.f;
    if (i < Bz*VOUTn) out0[i] = ((i & (VOUTn-1)) == 0) ? 1.f : 0.f;
    if (i < Bz)       idx[i] = 0;
}

// ---------------- driver ----------------
extern "C" void kernel_launch(void* const* d_in, const int* in_sizes, int n_in,
                              void* d_out, int out_size)
{
    const float* x       = (const float*)d_in[0];
    const int*   x_len   = (const int*)  d_in[1];
    const float* enc_Wih = (const float*)d_in[2];
    const float* enc_Whh = (const float*)d_in[3];
    const float* enc_bih = (const float*)d_in[4];
    const float* enc_bhh = (const float*)d_in[5];
    const float* dec_Wih = (const float*)d_in[6];
    const float* dec_Whh = (const float*)d_in[7];
    const float* dec_bih = (const float*)d_in[8];
    const float* dec_bhh = (const float*)d_in[9];
    const float* o2h_W   = (const float*)d_in[10];
    const float* o2h_b   = (const float*)d_in[11];
    const float* fc_W    = (const float*)d_in[12];
    const float* fc_b    = (const float*)d_in[13];
    const float* W1_W    = (const float*)d_in[14];
    const float* W1_b    = (const float*)d_in[15];
    const float* W2_W    = (const float*)d_in[16];
    const float* W2_b    = (const float*)d_in[17];
    const float* V_W     = (const float*)d_in[18];
    const float* V_b     = (const float*)d_in[19];
    float* out = (float*)d_out;

    float *gi_enc, *enc_out, *enc_proj, *h, *ghp, *gip, *qghp, *ctx, *fcp;
    float *Wqgh, *bqgh, *T, *Aemb, *zerob;
    int* idx;
    cudaGetSymbolAddress((void**)&gi_enc,   g_gi_enc);
    cudaGetSymbolAddress((void**)&enc_out,  g_enc_out);
    cudaGetSymbolAddress((void**)&enc_proj, g_enc_proj);
    cudaGetSymbolAddress((void**)&h,        g_h);
    cudaGetSymbolAddress((void**)&ghp,      g_ghp);
    cudaGetSymbolAddress((void**)&gip,      g_gip);
    cudaGetSymbolAddress((void**)&qghp,     g_qghp);
    cudaGetSymbolAddress((void**)&ctx,      g_ctx);
    cudaGetSymbolAddress((void**)&fcp,      g_fcp);
    cudaGetSymbolAddress((void**)&idx,      g_idx);
    cudaGetSymbolAddress((void**)&Wqgh,     g_Wqgh);
    cudaGetSymbolAddress((void**)&bqgh,     g_bqgh);
    cudaGetSymbolAddress((void**)&T,        g_T);
    cudaGetSymbolAddress((void**)&Aemb,     g_Aemb);
    cudaGetSymbolAddress((void**)&zerob,    g_zero);

    // ---- one-time prep ----
    prep<<<(NQGH*UU)/256, 256>>>(dec_Whh, W2_W, dec_bhh, W2_b, o2h_W, o2h_b,
                                 Wqgh, bqgh, Aemb);
    init_all<<<((size_t)Sn*Bz*UU)/256, 256>>>(enc_out, h, out, idx);
    // emb->gi table: T[128,3U] = Aemb[128,512] @ dec_Wih[:,U:U+E]^T + dec_bih
    gemm2<<<dim3(G3U/128, VOUTn/64, 1), 128>>>(Aemb, EE, dec_Wih + UU, UU+EE,
                                               dec_bih, T, VOUTn, G3U, EE, 1,
                                               nullptr, -1);
    // encoder input gates, all steps (skip fully-masked tiles)
    gemm2<<<dim3(G3U/128, (Sn*Bz)/64, 1), 128>>>(x, VIN, enc_Wih, VIN, enc_bih,
                                                 gi_enc, Sn*Bz, G3U, VIN, 1,
                                                 x_len, -1);

    // ---- Encoder: 64 sequential GRU steps (active-suffix only) ----
    for (int t = 0; t < Sn; t++) {
        gemm2<<<dim3(G3U/128, Bz/64, GHKS), 128>>>(h, UU, enc_Whh, UU, enc_bhh,
                                                   ghp, Bz, G3U, UU, GHKS,
                                                   x_len, t);
        enc_gate<<<(Bz*UU)/256, 256>>>(gi_enc + (size_t)t*Bz*G3U, ghp, h,
                                       enc_out + (size_t)t*Bz*UU, x_len, t);
    }

    // enc_proj = enc_out @ W1^T + b (masked rows never read downstream)
    gemm2<<<dim3(UU/128, (Sn*Bz)/64, 1), 128>>>(enc_out, UU, W1_W, UU, W1_b,
                                                enc_proj, Sn*Bz, UU, UU, 1,
                                                x_len, -1);

    // ---- Decoder: 24 sequential attention+GRU steps ----
    for (int t = 0; t < TDEC - 1; t++) {
        // merged [gh | q] GEMM: h @ [Whh;W2]^T, N=4096, one full wave
        gemm2<<<dim3(NQGH/128, Bz/64, QGHKS), 128>>>(h, UU, Wqgh, UU, bqgh,
                                                     qghp, Bz, NQGH, UU, QGHKS,
                                                     nullptr, -1);
        fused_attn<<<Bz, 256>>>(qghp, enc_proj, enc_out, V_W, V_b, W1_b,
                                x_len, ctx);
        // gi (ctx part only; emb part comes from table in dec_gate)
        gemm2<<<dim3(G3U/128, Bz/64, GIKS), 128>>>(ctx, UU, dec_Wih, UU+EE,
                                                   zerob, gip, Bz, G3U, UU,
                                                   GIKS, nullptr, -1);
        dec_gate<<<(Bz*UU)/256, 256>>>(gip, qghp, T, idx, h);
        gemm2<<<dim3(VOUTn/128, Bz/64, FCKS), 128>>>(h, UU, fc_W, UU, fc_b,
                                                     fcp, Bz, VOUTn, UU, FCKS,
                                                     nullptr, -1);
        pred_argmax<<<Bz, 128>>>(fcp, out + (size_t)(t+1)*Bz*VOUTn, idx);
    }
}